// round 6
// baseline (speedup 1.0000x reference)
#include <cuda_runtime.h>

// Problem dims
#define NB 8
#define DD 32   // d1=d2=d3
#define NC 32   // in_features
#define NO 32   // out_features
// positions = NB*DD*DD*DD = 262144

typedef unsigned long long ull;

// ---------------- scratch (device globals; no allocation allowed) ----------------
__device__ float g_m1[NB*DD*DD*NC];   // [b][j][k][c]  sum over i
__device__ float g_m2[NB*DD*DD*NC];   // [b][i][k][c]  sum over j
__device__ float g_m3[NB*DD*DD*NC];   // [b][i][j][c]  sum over k
__device__ float g_pij[NB*DD*NO];     // [b][k][o]
__device__ float g_pik[NB*DD*NO];     // [b][j][o]
__device__ float g_pjk[NB*DD*NO];     // [b][i][o]
__device__ float g_pall[NB*NO];       // [b][o]  (includes bias)
__device__ float g_PA[NB*DD*DD*NO];   // [b][j][k][o]
__device__ float g_PB[NB*DD*DD*NO];   // [b][i][k][o]
__device__ float g_PC[NB*DD*DD*NO];   // [b][i][j][o]

// ---------------- packed f32x2 helpers ----------------
__device__ __forceinline__ ull pack_dup(float v) {
    ull r;
    asm("mov.b64 %0, {%1, %1};" : "=l"(r) : "r"(__float_as_uint(v)));
    return r;
}
__device__ __forceinline__ float2 unpack2(ull v) {
    float2 r;
    asm("mov.b64 {%0, %1}, %2;" : "=f"(r.x), "=f"(r.y) : "l"(v));
    return r;
}
#define FMA2(acc, a, b) asm("fma.rn.f32x2 %0, %1, %2, %0;" : "+l"(acc) : "l"(a), "l"(b))

// ---------------- K1: axis sums m1,m2,m3 (grid 768) ----------------
__global__ __launch_bounds__(256) void k_means(const float* __restrict__ x) {
    int sel = blockIdx.x >> 8;        // 0:m1, 1:m2, 2:m3
    int blk = blockIdx.x & 255;
    int b = blk >> 5, d = blk & 31;
    int t = threadIdx.x;
    const float4* x4 = (const float4*)x;

    if (sel == 0) {
        float4 acc = make_float4(0.f, 0.f, 0.f, 0.f);
        #pragma unroll 8
        for (int i = 0; i < DD; i++) {
            float4 v = x4[((b * DD + i) * DD + d) * 256 + t];
            acc.x += v.x; acc.y += v.y; acc.z += v.z; acc.w += v.w;
        }
        ((float4*)g_m1)[(b * DD + d) * 256 + t] = acc;
    } else if (sel == 1) {
        float4 acc = make_float4(0.f, 0.f, 0.f, 0.f);
        #pragma unroll 8
        for (int j = 0; j < DD; j++) {
            float4 v = x4[((b * DD + d) * DD + j) * 256 + t];
            acc.x += v.x; acc.y += v.y; acc.z += v.z; acc.w += v.w;
        }
        ((float4*)g_m2)[(b * DD + d) * 256 + t] = acc;
    } else {
        int j = t >> 3, c4 = t & 7;
        float4 acc = make_float4(0.f, 0.f, 0.f, 0.f);
        #pragma unroll 8
        for (int k = 0; k < DD; k++) {
            float4 v = x4[((b * DD + d) * DD + j) * 256 + k * 8 + c4];
            acc.x += v.x; acc.y += v.y; acc.z += v.z; acc.w += v.w;
        }
        ((float4*)g_m3)[(b * DD + d) * 256 + j * 8 + c4] = acc;
    }
}

// ---------------- K2: fused 2/3-axis pools + small projections (grid 776) ----------------
__global__ __launch_bounds__(128) void k_small(const float* __restrict__ W,
                                               const float* __restrict__ bias) {
    __shared__ float part[128];
    __shared__ float mrow[NC];
    int gid = blockIdx.x;
    int t = threadIdx.x;
    int c = t & 31, q = t >> 5;     // q in 0..3

    float s = 0.f;
    const float* w;
    float scale;
    float* dst;
    bool addb = false;

    if (gid < 256) {
        int b = gid >> 5, k = gid & 31;
        #pragma unroll
        for (int j = q; j < DD; j += 4) s += g_m1[((b * DD + j) * DD + k) * NC + c];
        w = W + 128; scale = 1.0f / 1024.0f; dst = g_pij + gid * NO;
    } else if (gid < 512) {
        int g = gid - 256;
        int b = g >> 5, j = g & 31;
        #pragma unroll
        for (int k = q; k < DD; k += 4) s += g_m1[((b * DD + j) * DD + k) * NC + c];
        w = W + 160; scale = 1.0f / 1024.0f; dst = g_pik + g * NO;
    } else if (gid < 768) {
        int g = gid - 512;
        int b = g >> 5, i = g & 31;
        #pragma unroll
        for (int k = q; k < DD; k += 4) s += g_m2[((b * DD + i) * DD + k) * NC + c];
        w = W + 192; scale = 1.0f / 1024.0f; dst = g_pjk + g * NO;
    } else {
        int b = gid - 768;
        for (int jk = q; jk < DD * DD; jk += 4) s += g_m1[(b * DD * DD + jk) * NC + c];
        w = W + 224; scale = 1.0f / 32768.0f; dst = g_pall + b * NO; addb = true;
    }
    part[t] = s;
    __syncthreads();
    if (t < 32) {
        mrow[t] = part[t] + part[t + 32] + part[t + 64] + part[t + 96];
    }
    __syncthreads();
    if (t < 32) {
        float acc = 0.f;
        #pragma unroll
        for (int cc = 0; cc < NC; cc++) acc += mrow[cc] * w[t * 256 + cc];
        acc *= scale;
        if (addb) acc += bias[t];
        dst[t] = acc;
    }
}

// ---------------- K3: PA/PB/PC projections of m1/m2/m3 (grid 192) ----------------
__global__ __launch_bounds__(256) void k_bigproj(const float* __restrict__ W) {
    int sel = blockIdx.x >> 6;       // 64 blocks per source (8192 rows each)
    __shared__ float Ws[NC * NO];    // [c][o], pre-scaled by 1/32
    {
        int idx = threadIdx.x;
        #pragma unroll
        for (int qq = 0; qq < 4; qq++, idx += 256) {
            int c = idx >> 5, o = idx & 31;
            Ws[idx] = W[o * 256 + (1 + sel) * 32 + c] * (1.0f / 32.0f);
        }
    }
    __syncthreads();

    int p = (blockIdx.x & 63) * 128 + (threadIdx.x >> 1);   // row within source
    int half = threadIdx.x & 1;                              // outputs [half*16, half*16+16)
    const float* src = (sel == 0) ? g_m1 : (sel == 1) ? g_m2 : g_m3;
    const float4* xr = (const float4*)(src + p * NC);

    ull acc[8];
    #pragma unroll
    for (int o2 = 0; o2 < 8; o2++) acc[o2] = 0ull;

    #pragma unroll
    for (int c4 = 0; c4 < 8; c4++) {
        float4 a4 = xr[c4];
        #pragma unroll
        for (int cc = 0; cc < 4; cc++) {
            ull av2 = pack_dup(((const float*)&a4)[cc]);
            const ull* wrow = (const ull*)(Ws + (c4 * 4 + cc) * NO + half * 16);
            #pragma unroll
            for (int o2 = 0; o2 < 8; o2++) FMA2(acc[o2], av2, wrow[o2]);
        }
    }

    int b = p >> 10, d1 = (p >> 5) & 31, d2 = p & 31;
    float add[16];
    #pragma unroll
    for (int o = 0; o < 16; o++) add[o] = 0.f;
    float* dst;
    if (sel == 0) {
        dst = g_PA;
        const float* px = g_pij + (b * 32 + d2) * NO + half * 16;  // [b][k]
        const float* py = g_pik + (b * 32 + d1) * NO + half * 16;  // [b][j]
        const float* pz = g_pall + b * NO + half * 16;
        #pragma unroll
        for (int o = 0; o < 16; o++) add[o] = px[o] + py[o] + pz[o];
    } else if (sel == 1) {
        dst = g_PB;
        const float* px = g_pjk + (b * 32 + d1) * NO + half * 16;  // [b][i]
        #pragma unroll
        for (int o = 0; o < 16; o++) add[o] = px[o];
    } else {
        dst = g_PC;
    }

    float4* dv = (float4*)(dst + p * NO + half * 16);
    #pragma unroll
    for (int o4 = 0; o4 < 4; o4++) {
        float2 v0 = unpack2(acc[o4 * 2]);
        float2 v1 = unpack2(acc[o4 * 2 + 1]);
        float4 r;
        r.x = v0.x + add[o4 * 4 + 0];
        r.y = v0.y + add[o4 * 4 + 1];
        r.z = v1.x + add[o4 * 4 + 2];
        r.w = v1.y + add[o4 * 4 + 3];
        dv[o4] = r;
    }
}

// ---------------- K4: main projection (grid 1024 x 256, 4 CTAs/SM) ----------------
// Block = 256 rows (fixed b,i; 8 j x 32 k). Thread (pg,og): rows pg*4..+3,
// outputs og*8..+7, row-paired f32x2 accumulators.
// x transposed x_t[c][row] (stride 268): 1 LDS.128 per c -> 4 rows, no MOVs.
// W duplicated Wd[og][c][8] (stride 258 ull): 4 broadcast LDS.128 per c.
// PB/PC staged in smem (block-invariant i). PA read via 2 LDG.128 per row.
#define XTS 268
#define WSEC 258
__global__ __launch_bounds__(256, 4) void k_main(const float* __restrict__ x,
                                                 const float* __restrict__ W,
                                                 float* __restrict__ out) {
    __shared__ __align__(16) float x_t[NC * XTS];   // 34304 B
    __shared__ __align__(16) ull   Wd[4 * WSEC];    // 8256 B
    __shared__ __align__(16) float PBs[DD * NO];    // 4096 B  [k][o]
    __shared__ __align__(16) float PCs[8 * NO];     // 1024 B  [jj][o]

    int tid = threadIdx.x;
    int p0 = blockIdx.x * 256;
    int b = p0 >> 15, i = (p0 >> 10) & 31, j0 = (p0 >> 5) & 31;  // 8 j values

    // ---- stage W dup'd ----
    #pragma unroll
    for (int idx = tid; idx < 1024; idx += 256) {
        int og_ = idx >> 8, rem = idx & 255;
        int c = rem >> 3, oo = rem & 7;
        Wd[og_ * WSEC + c * 8 + oo] = pack_dup(W[(og_ * 8 + oo) * 256 + c]);
    }
    // ---- stage PB (1024 floats) and PC (256 floats) ----
    {
        const float4* pbsrc = (const float4*)(g_PB + ((b * 32 + i) * 32) * 32);
        ((float4*)PBs)[tid] = pbsrc[tid];               // PB[k][o] for all 32 k
        int jj = tid >> 5, o = tid & 31;
        PCs[tid] = g_PC[(((b * 32 + i) * 32) + j0 + jj) * 32 + o];
    }
    // ---- stage x transposed: x_t[c][row] ----
    {
        int c = tid & 31, rg8 = tid >> 5;       // rows rg8*32..+31
        const float* xb = x + (size_t)p0 * 32 + c;
        #pragma unroll
        for (int qq = 0; qq < 8; qq++) {
            int row4 = rg8 * 32 + qq * 4;
            float4 v;
            v.x = xb[(row4 + 0) * 32];
            v.y = xb[(row4 + 1) * 32];
            v.z = xb[(row4 + 2) * 32];
            v.w = xb[(row4 + 3) * 32];
            *(float4*)(x_t + c * XTS + row4) = v;   // STS.128, 4-phase minimum
        }
    }
    __syncthreads();

    int pg = tid >> 2;          // 0..63 : row group (4 rows)
    int og = tid & 3;           // 0..3  : output group (8 outputs)

    const float* xr = x_t + pg * 4;
    const ull*   wp = Wd + og * WSEC;

    ull accA[8], accB[8];       // accA: rows (+0,+1); accB: rows (+2,+3)
    #pragma unroll
    for (int o = 0; o < 8; o++) { accA[o] = 0ull; accB[o] = 0ull; }

    #pragma unroll
    for (int c = 0; c < NC; c++) {
        ulonglong2 u = *(const ulonglong2*)(xr + c * XTS);          // rows 0..3 at col c
        ulonglong2 w01 = *(const ulonglong2*)(wp + c * 8);
        ulonglong2 w23 = *(const ulonglong2*)(wp + c * 8 + 2);
        ulonglong2 w45 = *(const ulonglong2*)(wp + c * 8 + 4);
        ulonglong2 w67 = *(const ulonglong2*)(wp + c * 8 + 6);
        FMA2(accA[0], u.x, w01.x); FMA2(accA[1], u.x, w01.y);
        FMA2(accA[2], u.x, w23.x); FMA2(accA[3], u.x, w23.y);
        FMA2(accA[4], u.x, w45.x); FMA2(accA[5], u.x, w45.y);
        FMA2(accA[6], u.x, w67.x); FMA2(accA[7], u.x, w67.y);
        FMA2(accB[0], u.y, w01.x); FMA2(accB[1], u.y, w01.y);
        FMA2(accB[2], u.y, w23.x); FMA2(accB[3], u.y, w23.y);
        FMA2(accB[4], u.y, w45.x); FMA2(accB[5], u.y, w45.y);
        FMA2(accB[6], u.y, w67.x); FMA2(accB[7], u.y, w67.y);
    }

    // ---- epilogue: + PA(gmem) + PB(smem) + PC(smem), store out ----
    #pragma unroll
    for (int rr = 0; rr < 4; rr++) {
        int rl = pg * 4 + rr;               // 0..255
        int k = rl & 31, jj = rl >> 5;
        const float4* pa = (const float4*)(g_PA + ((((b * 32 + j0 + jj) * 32 + k) * 32) + og * 8));
        const float4* pb = (const float4*)(PBs + k * 32 + og * 8);
        const float4* pc = (const float4*)(PCs + jj * 32 + og * 8);
        float4 a0 = pa[0], a1 = pa[1];
        float4 b0 = pb[0], b1 = pb[1];
        float4 c0 = pc[0], c1 = pc[1];
        // lazy unpack: low/high half of the acc pair is just a register name
        float v0, v1, v2, v3, v4, v5, v6, v7;
        if (rr == 0) {
            v0 = unpack2(accA[0]).x; v1 = unpack2(accA[1]).x; v2 = unpack2(accA[2]).x; v3 = unpack2(accA[3]).x;
            v4 = unpack2(accA[4]).x; v5 = unpack2(accA[5]).x; v6 = unpack2(accA[6]).x; v7 = unpack2(accA[7]).x;
        } else if (rr == 1) {
            v0 = unpack2(accA[0]).y; v1 = unpack2(accA[1]).y; v2 = unpack2(accA[2]).y; v3 = unpack2(accA[3]).y;
            v4 = unpack2(accA[4]).y; v5 = unpack2(accA[5]).y; v6 = unpack2(accA[6]).y; v7 = unpack2(accA[7]).y;
        } else if (rr == 2) {
            v0 = unpack2(accB[0]).x; v1 = unpack2(accB[1]).x; v2 = unpack2(accB[2]).x; v3 = unpack2(accB[3]).x;
            v4 = unpack2(accB[4]).x; v5 = unpack2(accB[5]).x; v6 = unpack2(accB[6]).x; v7 = unpack2(accB[7]).x;
        } else {
            v0 = unpack2(accB[0]).y; v1 = unpack2(accB[1]).y; v2 = unpack2(accB[2]).y; v3 = unpack2(accB[3]).y;
            v4 = unpack2(accB[4]).y; v5 = unpack2(accB[5]).y; v6 = unpack2(accB[6]).y; v7 = unpack2(accB[7]).y;
        }
        float4 r0, r1;
        r0.x = v0 + a0.x + b0.x + c0.x;
        r0.y = v1 + a0.y + b0.y + c0.y;
        r0.z = v2 + a0.z + b0.z + c0.z;
        r0.w = v3 + a0.w + b0.w + c0.w;
        r1.x = v4 + a1.x + b1.x + c1.x;
        r1.y = v5 + a1.y + b1.y + c1.y;
        r1.z = v6 + a1.z + b1.z + c1.z;
        r1.w = v7 + a1.w + b1.w + c1.w;
        float4* dst = (float4*)(out + (size_t)(p0 + rl) * 32 + og * 8);
        dst[0] = r0;
        dst[1] = r1;
    }
}

// ---------------- launch ----------------
extern "C" void kernel_launch(void* const* d_in, const int* in_sizes, int n_in,
                              void* d_out, int out_size) {
    const float* x    = (const float*)d_in[0];
    const float* W    = (const float*)d_in[1];
    const float* bias = (const float*)d_in[2];
    float* out = (float*)d_out;

    k_means<<<768, 256>>>(x);
    k_small<<<776, 128>>>(W, bias);
    k_bigproj<<<192, 256>>>(W);
    k_main<<<1024, 256>>>(x, W, out);
}

// round 8
// speedup vs baseline: 1.0327x; 1.0327x over previous
#include <cuda_runtime.h>
#include <cuda_bf16.h>
#include <cstdint>

// Problem dims
#define NB 8
#define DD 32
#define NC 32
#define NO 32
// positions = 262144

typedef unsigned long long ull;

// ---------------- scratch ----------------
__device__ float g_m1[NB*DD*DD*NC];
__device__ float g_m2[NB*DD*DD*NC];
__device__ float g_m3[NB*DD*DD*NC];
__device__ float g_pij[NB*DD*NO];
__device__ float g_pik[NB*DD*NO];
__device__ float g_pjk[NB*DD*NO];
__device__ float g_pall[NB*NO];
__device__ float g_PA[NB*DD*DD*NO];
__device__ float g_PB[NB*DD*DD*NO];
__device__ float g_PC[NB*DD*DD*NO];

// ---------------- helpers ----------------
__device__ __forceinline__ ull pack_dup(float v) {
    ull r; asm("mov.b64 %0, {%1, %1};" : "=l"(r) : "r"(__float_as_uint(v))); return r;
}
__device__ __forceinline__ float2 unpack2(ull v) {
    float2 r; asm("mov.b64 {%0, %1}, %2;" : "=f"(r.x), "=f"(r.y) : "l"(v)); return r;
}
#define FMA2(acc, a, b) asm("fma.rn.f32x2 %0, %1, %2, %0;" : "+l"(acc) : "l"(a), "l"(b))

// fp32 pair -> (hi, lo) bf16x2 (element0 = first value in low half)
__device__ __forceinline__ void split_pair(float a, float b, uint32_t& hi, uint32_t& lo) {
    __nv_bfloat162 h = __floats2bfloat162_rn(a, b);
    float2 hf = __bfloat1622float2(h);
    __nv_bfloat162 l = __floats2bfloat162_rn(a - hf.x, b - hf.y);
    hi = *(uint32_t*)&h;
    lo = *(uint32_t*)&l;
}

#define MMA16816(d, a, b) \
    asm volatile("mma.sync.aligned.m16n8k16.row.col.f32.bf16.bf16.f32 " \
                 "{%0,%1,%2,%3}, {%4,%5,%6,%7}, {%8,%9}, {%0,%1,%2,%3};" \
                 : "+f"(d[0]), "+f"(d[1]), "+f"(d[2]), "+f"(d[3]) \
                 : "r"(a[0]), "r"(a[1]), "r"(a[2]), "r"(a[3]), "r"(b[0]), "r"(b[1]))

// ---------------- K1: axis sums (grid 768) ----------------
__global__ __launch_bounds__(256) void k_means(const float* __restrict__ x) {
    int sel = blockIdx.x >> 8;
    int blk = blockIdx.x & 255;
    int b = blk >> 5, d = blk & 31;
    int t = threadIdx.x;
    const float4* x4 = (const float4*)x;

    if (sel == 0) {
        float4 acc = make_float4(0.f, 0.f, 0.f, 0.f);
        #pragma unroll 8
        for (int i = 0; i < DD; i++) {
            float4 v = x4[((b * DD + i) * DD + d) * 256 + t];
            acc.x += v.x; acc.y += v.y; acc.z += v.z; acc.w += v.w;
        }
        ((float4*)g_m1)[(b * DD + d) * 256 + t] = acc;
    } else if (sel == 1) {
        float4 acc = make_float4(0.f, 0.f, 0.f, 0.f);
        #pragma unroll 8
        for (int j = 0; j < DD; j++) {
            float4 v = x4[((b * DD + d) * DD + j) * 256 + t];
            acc.x += v.x; acc.y += v.y; acc.z += v.z; acc.w += v.w;
        }
        ((float4*)g_m2)[(b * DD + d) * 256 + t] = acc;
    } else {
        int j = t >> 3, c4 = t & 7;
        float4 acc = make_float4(0.f, 0.f, 0.f, 0.f);
        #pragma unroll 8
        for (int k = 0; k < DD; k++) {
            float4 v = x4[((b * DD + d) * DD + j) * 256 + k * 8 + c4];
            acc.x += v.x; acc.y += v.y; acc.z += v.z; acc.w += v.w;
        }
        ((float4*)g_m3)[(b * DD + d) * 256 + j * 8 + c4] = acc;
    }
}

// ---------------- K2: pools + small projections (grid 776) ----------------
__global__ __launch_bounds__(128) void k_small(const float* __restrict__ W,
                                               const float* __restrict__ bias) {
    __shared__ float part[128];
    __shared__ float mrow[NC];
    int gid = blockIdx.x;
    int t = threadIdx.x;
    int c = t & 31, q = t >> 5;

    float s = 0.f;
    const float* w;
    float scale;
    float* dst;
    bool addb = false;

    if (gid < 256) {
        int b = gid >> 5, k = gid & 31;
        #pragma unroll
        for (int j = q; j < DD; j += 4) s += g_m1[((b * DD + j) * DD + k) * NC + c];
        w = W + 128; scale = 1.0f / 1024.0f; dst = g_pij + gid * NO;
    } else if (gid < 512) {
        int g = gid - 256;
        int b = g >> 5, j = g & 31;
        #pragma unroll
        for (int k = q; k < DD; k += 4) s += g_m1[((b * DD + j) * DD + k) * NC + c];
        w = W + 160; scale = 1.0f / 1024.0f; dst = g_pik + g * NO;
    } else if (gid < 768) {
        int g = gid - 512;
        int b = g >> 5, i = g & 31;
        #pragma unroll
        for (int k = q; k < DD; k += 4) s += g_m2[((b * DD + i) * DD + k) * NC + c];
        w = W + 192; scale = 1.0f / 1024.0f; dst = g_pjk + g * NO;
    } else {
        int b = gid - 768;
        for (int jk = q; jk < DD * DD; jk += 4) s += g_m1[(b * DD * DD + jk) * NC + c];
        w = W + 224; scale = 1.0f / 32768.0f; dst = g_pall + b * NO; addb = true;
    }
    part[t] = s;
    __syncthreads();
    if (t < 32) mrow[t] = part[t] + part[t + 32] + part[t + 64] + part[t + 96];
    __syncthreads();
    if (t < 32) {
        float acc = 0.f;
        #pragma unroll
        for (int cc = 0; cc < NC; cc++) acc += mrow[cc] * w[t * 256 + cc];
        acc *= scale;
        if (addb) acc += bias[t];
        dst[t] = acc;
    }
}

// ---------------- K3: PA/PB/PC projections (grid 192) ----------------
__global__ __launch_bounds__(256) void k_bigproj(const float* __restrict__ W) {
    int sel = blockIdx.x >> 6;
    __shared__ float Ws[NC * NO];
    {
        int idx = threadIdx.x;
        #pragma unroll
        for (int qq = 0; qq < 4; qq++, idx += 256) {
            int c = idx >> 5, o = idx & 31;
            Ws[idx] = W[o * 256 + (1 + sel) * 32 + c] * (1.0f / 32.0f);
        }
    }
    __syncthreads();

    int p = (blockIdx.x & 63) * 128 + (threadIdx.x >> 1);
    int half = threadIdx.x & 1;
    const float* src = (sel == 0) ? g_m1 : (sel == 1) ? g_m2 : g_m3;
    const float4* xr = (const float4*)(src + p * NC);

    ull acc[8];
    #pragma unroll
    for (int o2 = 0; o2 < 8; o2++) acc[o2] = 0ull;

    #pragma unroll
    for (int c4 = 0; c4 < 8; c4++) {
        float4 a4 = xr[c4];
        #pragma unroll
        for (int cc = 0; cc < 4; cc++) {
            ull av2 = pack_dup(((const float*)&a4)[cc]);
            const ull* wrow = (const ull*)(Ws + (c4 * 4 + cc) * NO + half * 16);
            #pragma unroll
            for (int o2 = 0; o2 < 8; o2++) FMA2(acc[o2], av2, wrow[o2]);
        }
    }

    int b = p >> 10, d1 = (p >> 5) & 31, d2 = p & 31;
    float add[16];
    #pragma unroll
    for (int o = 0; o < 16; o++) add[o] = 0.f;
    float* dst;
    if (sel == 0) {
        dst = g_PA;
        const float* px = g_pij + (b * 32 + d2) * NO + half * 16;
        const float* py = g_pik + (b * 32 + d1) * NO + half * 16;
        const float* pz = g_pall + b * NO + half * 16;
        #pragma unroll
        for (int o = 0; o < 16; o++) add[o] = px[o] + py[o] + pz[o];
    } else if (sel == 1) {
        dst = g_PB;
        const float* px = g_pjk + (b * 32 + d1) * NO + half * 16;
        #pragma unroll
        for (int o = 0; o < 16; o++) add[o] = px[o];
    } else {
        dst = g_PC;
    }

    float4* dv = (float4*)(dst + p * NO + half * 16);
    #pragma unroll
    for (int o4 = 0; o4 < 4; o4++) {
        float2 v0 = unpack2(acc[o4 * 2]);
        float2 v1 = unpack2(acc[o4 * 2 + 1]);
        float4 r;
        r.x = v0.x + add[o4 * 4 + 0];
        r.y = v0.y + add[o4 * 4 + 1];
        r.z = v1.x + add[o4 * 4 + 2];
        r.w = v1.y + add[o4 * 4 + 3];
        dv[o4] = r;
    }
}

// ---------------- K4: main projection via mma.sync bf16 split (grid 2048 x 256) ----------------
// One warp = one m16 tile (16 rows x 32 outs x K=32). No smem, no ldmatrix:
// A fragments LDG.64 direct from x (row-major matches m16n8k16 A layout),
// B fragments (W) computed once into registers, D = Ahi*Bhi + Ahi*Blo + Alo*Bhi.
__global__ __launch_bounds__(256) void k_main_mma(const float* __restrict__ x,
                                                  const float* __restrict__ W,
                                                  float* __restrict__ out) {
    int tid = threadIdx.x;
    int wid = tid >> 5, lid = tid & 31;
    int wt = blockIdx.x * 8 + wid;       // warp tile id, 0..16383
    int p0 = wt * 16;                     // 16 rows
    int lr = lid >> 2;                    // 0..7
    int lc2 = (lid & 3) * 2;              // 0,2,4,6

    // ---- B fragments from W (col-major k x n per chunk) ----
    uint32_t Bh[2][4][2], Bl[2][4][2];
    #pragma unroll
    for (int kc = 0; kc < 2; kc++) {
        #pragma unroll
        for (int nc = 0; nc < 4; nc++) {
            int o = nc * 8 + lr;
            int c = kc * 16 + lc2;
            float2 w0 = *(const float2*)(W + o * 256 + c);
            float2 w1 = *(const float2*)(W + o * 256 + c + 8);
            split_pair(w0.x, w0.y, Bh[kc][nc][0], Bl[kc][nc][0]);
            split_pair(w1.x, w1.y, Bh[kc][nc][1], Bl[kc][nc][1]);
        }
    }

    // ---- A fragments from x ----
    uint32_t Ah[2][4], Al[2][4];
    const float* xr0 = x + (size_t)(p0 + lr) * 32;
    const float* xr1 = x + (size_t)(p0 + lr + 8) * 32;
    #pragma unroll
    for (int kc = 0; kc < 2; kc++) {
        int c = kc * 16 + lc2;
        float2 f0 = *(const float2*)(xr0 + c);        // (row, k)
        float2 f1 = *(const float2*)(xr1 + c);        // (row+8, k)
        float2 f2 = *(const float2*)(xr0 + c + 8);    // (row, k+8)
        float2 f3 = *(const float2*)(xr1 + c + 8);    // (row+8, k+8)
        split_pair(f0.x, f0.y, Ah[kc][0], Al[kc][0]);
        split_pair(f1.x, f1.y, Ah[kc][1], Al[kc][1]);
        split_pair(f2.x, f2.y, Ah[kc][2], Al[kc][2]);
        split_pair(f3.x, f3.y, Ah[kc][3], Al[kc][3]);
    }

    // ---- MMAs ----
    float D[4][4];
    #pragma unroll
    for (int nc = 0; nc < 4; nc++)
        #pragma unroll
        for (int q = 0; q < 4; q++) D[nc][q] = 0.f;

    #pragma unroll
    for (int kc = 0; kc < 2; kc++) {
        #pragma unroll
        for (int nc = 0; nc < 4; nc++) {
            MMA16816(D[nc], Ah[kc], Bh[kc][nc]);
            MMA16816(D[nc], Ah[kc], Bl[kc][nc]);
            MMA16816(D[nc], Al[kc], Bh[kc][nc]);
        }
    }

    // ---- epilogue: + PA + PB + PC, direct float2 stores ----
    #pragma unroll
    for (int half = 0; half < 2; half++) {
        int gr = p0 + lr + half * 8;
        int k = gr & 31, j = (gr >> 5) & 31, i = (gr >> 10) & 31, b = gr >> 15;
        const float* PA = g_PA + (((b * 32 + j) * 32 + k) * 32);
        const float* PB = g_PB + (((b * 32 + i) * 32 + k) * 32);
        const float* PC = g_PC + (((b * 32 + i) * 32 + j) * 32);
        float* og = out + (size_t)gr * 32;
        #pragma unroll
        for (int nc = 0; nc < 4; nc++) {
            int col = nc * 8 + lc2;
            float2 pa = *(const float2*)(PA + col);
            float2 pb = *(const float2*)(PB + col);
            float2 pc = *(const float2*)(PC + col);
            float2 r;
            r.x = D[nc][half * 2 + 0] + pa.x + pb.x + pc.x;
            r.y = D[nc][half * 2 + 1] + pa.y + pb.y + pc.y;
            *(float2*)(og + col) = r;
        }
    }
}

// ---------------- launch ----------------
extern "C" void kernel_launch(void* const* d_in, const int* in_sizes, int n_in,
                              void* d_out, int out_size) {
    const float* x    = (const float*)d_in[0];
    const float* W    = (const float*)d_in[1];
    const float* bias = (const float*)d_in[2];
    float* out = (float*)d_out;

    k_means<<<768, 256>>>(x);
    k_small<<<776, 128>>>(W, bias);
    k_bigproj<<<192, 256>>>(W);
    k_main_mma<<<2048, 256>>>(x, W, out);
}

// round 9
// speedup vs baseline: 1.2640x; 1.2240x over previous
#include <cuda_runtime.h>
#include <cuda_bf16.h>
#include <cstdint>

// Problem dims
#define NB 8
#define DD 32
#define NC 32
#define NO 32
// positions = 262144

typedef unsigned long long ull;

// ---------------- scratch ----------------
__device__ float g_m1[NB*DD*DD*NC];
__device__ float g_m2[NB*DD*DD*NC];
__device__ float g_m3[NB*DD*DD*NC];
__device__ float g_pij[NB*DD*NO];
__device__ float g_pik[NB*DD*NO];
__device__ float g_pjk[NB*DD*NO];
__device__ float g_pall[NB*NO];
__device__ float g_PA[NB*DD*DD*NO];
__device__ float g_PB[NB*DD*DD*NO];
__device__ float g_PC[NB*DD*DD*NO];

// ---------------- helpers ----------------
__device__ __forceinline__ ull pack_dup(float v) {
    ull r; asm("mov.b64 %0, {%1, %1};" : "=l"(r) : "r"(__float_as_uint(v))); return r;
}
__device__ __forceinline__ float2 unpack2(ull v) {
    float2 r; asm("mov.b64 {%0, %1}, %2;" : "=f"(r.x), "=f"(r.y) : "l"(v)); return r;
}
#define FMA2(acc, a, b) asm("fma.rn.f32x2 %0, %1, %2, %0;" : "+l"(acc) : "l"(a), "l"(b))

// fp32 pair -> (hi, lo) bf16x2
__device__ __forceinline__ void split_pair(float a, float b, uint32_t& hi, uint32_t& lo) {
    __nv_bfloat162 h = __floats2bfloat162_rn(a, b);
    float2 hf = __bfloat1622float2(h);
    __nv_bfloat162 l = __floats2bfloat162_rn(a - hf.x, b - hf.y);
    hi = *(uint32_t*)&h;
    lo = *(uint32_t*)&l;
}

#define MMA16816(d, a, b) \
    asm volatile("mma.sync.aligned.m16n8k16.row.col.f32.bf16.bf16.f32 " \
                 "{%0,%1,%2,%3}, {%4,%5,%6,%7}, {%8,%9}, {%0,%1,%2,%3};" \
                 : "+f"(d[0]), "+f"(d[1]), "+f"(d[2]), "+f"(d[3]) \
                 : "r"(a[0]), "r"(a[1]), "r"(a[2]), "r"(a[3]), "r"(b[0]), "r"(b[1]))

// ---------------- K1: axis sums (grid 768) ----------------
__global__ __launch_bounds__(256) void k_means(const float* __restrict__ x) {
    int sel = blockIdx.x >> 8;
    int blk = blockIdx.x & 255;
    int b = blk >> 5, d = blk & 31;
    int t = threadIdx.x;
    const float4* x4 = (const float4*)x;

    if (sel == 0) {
        float4 acc = make_float4(0.f, 0.f, 0.f, 0.f);
        #pragma unroll 8
        for (int i = 0; i < DD; i++) {
            float4 v = x4[((b * DD + i) * DD + d) * 256 + t];
            acc.x += v.x; acc.y += v.y; acc.z += v.z; acc.w += v.w;
        }
        ((float4*)g_m1)[(b * DD + d) * 256 + t] = acc;
    } else if (sel == 1) {
        float4 acc = make_float4(0.f, 0.f, 0.f, 0.f);
        #pragma unroll 8
        for (int j = 0; j < DD; j++) {
            float4 v = x4[((b * DD + d) * DD + j) * 256 + t];
            acc.x += v.x; acc.y += v.y; acc.z += v.z; acc.w += v.w;
        }
        ((float4*)g_m2)[(b * DD + d) * 256 + t] = acc;
    } else {
        int j = t >> 3, c4 = t & 7;
        float4 acc = make_float4(0.f, 0.f, 0.f, 0.f);
        #pragma unroll 8
        for (int k = 0; k < DD; k++) {
            float4 v = x4[((b * DD + d) * DD + j) * 256 + k * 8 + c4];
            acc.x += v.x; acc.y += v.y; acc.z += v.z; acc.w += v.w;
        }
        ((float4*)g_m3)[(b * DD + d) * 256 + j * 8 + c4] = acc;
    }
}

// ---------------- K2: pools + small projections (grid 776) ----------------
__global__ __launch_bounds__(128) void k_small(const float* __restrict__ W,
                                               const float* __restrict__ bias) {
    __shared__ float part[128];
    __shared__ float mrow[NC];
    int gid = blockIdx.x;
    int t = threadIdx.x;
    int c = t & 31, q = t >> 5;

    float s = 0.f;
    const float* w;
    float scale;
    float* dst;
    bool addb = false;

    if (gid < 256) {
        int b = gid >> 5, k = gid & 31;
        #pragma unroll
        for (int j = q; j < DD; j += 4) s += g_m1[((b * DD + j) * DD + k) * NC + c];
        w = W + 128; scale = 1.0f / 1024.0f; dst = g_pij + gid * NO;
    } else if (gid < 512) {
        int g = gid - 256;
        int b = g >> 5, j = g & 31;
        #pragma unroll
        for (int k = q; k < DD; k += 4) s += g_m1[((b * DD + j) * DD + k) * NC + c];
        w = W + 160; scale = 1.0f / 1024.0f; dst = g_pik + g * NO;
    } else if (gid < 768) {
        int g = gid - 512;
        int b = g >> 5, i = g & 31;
        #pragma unroll
        for (int k = q; k < DD; k += 4) s += g_m2[((b * DD + i) * DD + k) * NC + c];
        w = W + 192; scale = 1.0f / 1024.0f; dst = g_pjk + g * NO;
    } else {
        int b = gid - 768;
        for (int jk = q; jk < DD * DD; jk += 4) s += g_m1[(b * DD * DD + jk) * NC + c];
        w = W + 224; scale = 1.0f / 32768.0f; dst = g_pall + b * NO; addb = true;
    }
    part[t] = s;
    __syncthreads();
    if (t < 32) mrow[t] = part[t] + part[t + 32] + part[t + 64] + part[t + 96];
    __syncthreads();
    if (t < 32) {
        float acc = 0.f;
        #pragma unroll
        for (int cc = 0; cc < NC; cc++) acc += mrow[cc] * w[t * 256 + cc];
        acc *= scale;
        if (addb) acc += bias[t];
        dst[t] = acc;
    }
}

// ---------------- K3: PA/PB/PC projections (grid 192) ----------------
__global__ __launch_bounds__(256) void k_bigproj(const float* __restrict__ W) {
    int sel = blockIdx.x >> 6;
    __shared__ float Ws[NC * NO];
    {
        int idx = threadIdx.x;
        #pragma unroll
        for (int qq = 0; qq < 4; qq++, idx += 256) {
            int c = idx >> 5, o = idx & 31;
            Ws[idx] = W[o * 256 + (1 + sel) * 32 + c] * (1.0f / 32.0f);
        }
    }
    __syncthreads();

    int p = (blockIdx.x & 63) * 128 + (threadIdx.x >> 1);
    int half = threadIdx.x & 1;
    const float* src = (sel == 0) ? g_m1 : (sel == 1) ? g_m2 : g_m3;
    const float4* xr = (const float4*)(src + p * NC);

    ull acc[8];
    #pragma unroll
    for (int o2 = 0; o2 < 8; o2++) acc[o2] = 0ull;

    #pragma unroll
    for (int c4 = 0; c4 < 8; c4++) {
        float4 a4 = xr[c4];
        #pragma unroll
        for (int cc = 0; cc < 4; cc++) {
            ull av2 = pack_dup(((const float*)&a4)[cc]);
            const ull* wrow = (const ull*)(Ws + (c4 * 4 + cc) * NO + half * 16);
            #pragma unroll
            for (int o2 = 0; o2 < 8; o2++) FMA2(acc[o2], av2, wrow[o2]);
        }
    }

    int b = p >> 10, d1 = (p >> 5) & 31, d2 = p & 31;
    float add[16];
    #pragma unroll
    for (int o = 0; o < 16; o++) add[o] = 0.f;
    float* dst;
    if (sel == 0) {
        dst = g_PA;
        const float* px = g_pij + (b * 32 + d2) * NO + half * 16;
        const float* py = g_pik + (b * 32 + d1) * NO + half * 16;
        const float* pz = g_pall + b * NO + half * 16;
        #pragma unroll
        for (int o = 0; o < 16; o++) add[o] = px[o] + py[o] + pz[o];
    } else if (sel == 1) {
        dst = g_PB;
        const float* px = g_pjk + (b * 32 + d1) * NO + half * 16;
        #pragma unroll
        for (int o = 0; o < 16; o++) add[o] = px[o];
    } else {
        dst = g_PC;
    }

    float4* dv = (float4*)(dst + p * NO + half * 16);
    #pragma unroll
    for (int o4 = 0; o4 < 4; o4++) {
        float2 v0 = unpack2(acc[o4 * 2]);
        float2 v1 = unpack2(acc[o4 * 2 + 1]);
        float4 r;
        r.x = v0.x + add[o4 * 4 + 0];
        r.y = v0.y + add[o4 * 4 + 1];
        r.z = v1.x + add[o4 * 4 + 2];
        r.w = v1.y + add[o4 * 4 + 3];
        dv[o4] = r;
    }
}

// ---------------- K4: mma.sync main projection, smem-staged (grid 2048 x 128) ----------------
// Block = 128 rows. Warp w: rows w*32..+31 as two m16n32 tiles.
// x_s stride 40 floats: fragment LDS.64 banks (8*lr + lc2) mod 32 -> distinct
// per 16-lane phase; STS.128/LDS.128 phases conflict-free. D is stored back
// over the (dead) x rows, then a fully coalesced float4 epilogue adds PA/PB/PC.
#define XRS 40
__global__ __launch_bounds__(128) void k_main_mma(const float* __restrict__ x,
                                                  const float* __restrict__ W,
                                                  float* __restrict__ out) {
    __shared__ __align__(16) float x_s[128 * XRS];   // 20480 B, reused for result
    __shared__ __align__(16) float W_s[32 * XRS];    // 5120 B

    int tid = threadIdx.x;
    int wid = tid >> 5, lid = tid & 31;
    int lr = lid >> 2;               // 0..7
    int lc2 = (lid & 3) * 2;         // 0,2,4,6
    int p0 = blockIdx.x * 128;

    // ---- stage W group-0 [32 o][32 c] (coalesced LDG.128) ----
    #pragma unroll
    for (int idx = tid; idx < 256; idx += 128) {
        int o = idx >> 3, c4 = idx & 7;
        float4 v = *(const float4*)(W + o * 256 + c4 * 4);
        *(float4*)(W_s + o * XRS + c4 * 4) = v;
    }
    // ---- stage x tile [128 rows][32 c] (coalesced LDG.128) ----
    {
        const float4* xg = (const float4*)(x + (size_t)p0 * 32);
        #pragma unroll
        for (int q = 0; q < 8; q++) {
            int idx = q * 128 + tid;
            int row = idx >> 3, c4 = idx & 7;
            float4 v = xg[idx];
            *(float4*)(x_s + row * XRS + c4 * 4) = v;
        }
    }
    __syncthreads();

    // ---- B fragments from W_s (conflict-free LDS.64) ----
    uint32_t Bh[2][4][2], Bl[2][4][2];
    #pragma unroll
    for (int kc = 0; kc < 2; kc++) {
        #pragma unroll
        for (int nc = 0; nc < 4; nc++) {
            int o = nc * 8 + lr;
            int c = kc * 16 + lc2;
            float2 w0 = *(const float2*)(W_s + o * XRS + c);
            float2 w1 = *(const float2*)(W_s + o * XRS + c + 8);
            split_pair(w0.x, w0.y, Bh[kc][nc][0], Bl[kc][nc][0]);
            split_pair(w1.x, w1.y, Bh[kc][nc][1], Bl[kc][nc][1]);
        }
    }

    // ---- two m16 tiles per warp; D overwrites own x_s rows (warp-local order) ----
    #pragma unroll
    for (int t = 0; t < 2; t++) {
        int rbase = wid * 32 + t * 16;
        uint32_t Ah[2][4], Al[2][4];
        #pragma unroll
        for (int kc = 0; kc < 2; kc++) {
            int c = kc * 16 + lc2;
            const float* r0 = x_s + (rbase + lr) * XRS;
            const float* r1 = x_s + (rbase + lr + 8) * XRS;
            float2 f0 = *(const float2*)(r0 + c);
            float2 f1 = *(const float2*)(r1 + c);
            float2 f2 = *(const float2*)(r0 + c + 8);
            float2 f3 = *(const float2*)(r1 + c + 8);
            split_pair(f0.x, f0.y, Ah[kc][0], Al[kc][0]);
            split_pair(f1.x, f1.y, Ah[kc][1], Al[kc][1]);
            split_pair(f2.x, f2.y, Ah[kc][2], Al[kc][2]);
            split_pair(f3.x, f3.y, Ah[kc][3], Al[kc][3]);
        }

        float D[4][4];
        #pragma unroll
        for (int nc = 0; nc < 4; nc++)
            #pragma unroll
            for (int q = 0; q < 4; q++) D[nc][q] = 0.f;

        #pragma unroll
        for (int kc = 0; kc < 2; kc++) {
            #pragma unroll
            for (int nc = 0; nc < 4; nc++) {
                MMA16816(D[nc], Ah[kc], Bh[kc][nc]);
                MMA16816(D[nc], Ah[kc], Bl[kc][nc]);
                MMA16816(D[nc], Al[kc], Bh[kc][nc]);
            }
        }

        // store D over the consumed x rows (conflict-free STS.64)
        #pragma unroll
        for (int half = 0; half < 2; half++) {
            int row = rbase + lr + half * 8;
            #pragma unroll
            for (int nc = 0; nc < 4; nc++) {
                *(float2*)(x_s + row * XRS + nc * 8 + lc2) =
                    make_float2(D[nc][half * 2 + 0], D[nc][half * 2 + 1]);
            }
        }
    }
    __syncthreads();

    // ---- coalesced epilogue: + PA + PB + PC, float4 everywhere ----
    {
        float4* og4 = (float4*)(out + (size_t)p0 * 32);
        #pragma unroll
        for (int q = 0; q < 8; q++) {
            int idx = q * 128 + tid;
            int rl = idx >> 3, o4 = idx & 7;
            int gr = p0 + rl;
            int k = gr & 31, j = (gr >> 5) & 31, i = (gr >> 10) & 31, b = gr >> 15;
            float4 v = *(const float4*)(x_s + rl * XRS + o4 * 4);
            float4 pa = ((const float4*)(g_PA + (((b * 32 + j) * 32 + k) * 32)))[o4];
            float4 pb = ((const float4*)(g_PB + (((b * 32 + i) * 32 + k) * 32)))[o4];
            float4 pc = ((const float4*)(g_PC + (((b * 32 + i) * 32 + j) * 32)))[o4];
            float4 r;
            r.x = v.x + pa.x + pb.x + pc.x;
            r.y = v.y + pa.y + pb.y + pc.y;
            r.z = v.z + pa.z + pb.z + pc.z;
            r.w = v.w + pa.w + pb.w + pc.w;
            og4[idx] = r;
        }
    }
}

// ---------------- launch ----------------
extern "C" void kernel_launch(void* const* d_in, const int* in_sizes, int n_in,
                              void* d_out, int out_size) {
    const float* x    = (const float*)d_in[0];
    const float* W    = (const float*)d_in[1];
    const float* bias = (const float*)d_in[2];
    float* out = (float*)d_out;

    k_means<<<768, 256>>>(x);
    k_small<<<776, 128>>>(W, bias);
    k_bigproj<<<192, 256>>>(W);
    k_main_mma<<<2048, 128>>>(x, W, out);
}

// round 10
// speedup vs baseline: 1.3373x; 1.0579x over previous
#include <cuda_runtime.h>
#include <cuda_bf16.h>
#include <cstdint>

// Problem dims
#define NB 8
#define DD 32
#define NC 32
#define NO 32
// positions = 262144

typedef unsigned long long ull;

// ---------------- scratch ----------------
__device__ float g_m1[NB*DD*DD*NC];
__device__ float g_m2[NB*DD*DD*NC];
__device__ float g_m3[NB*DD*DD*NC];
__device__ float g_pij[NB*DD*NO];
__device__ float g_pik[NB*DD*NO];
__device__ float g_pjk[NB*DD*NO];
__device__ float g_pall[NB*NO];
__device__ float g_PA[NB*DD*DD*NO];
__device__ float g_PB[NB*DD*DD*NO];
__device__ float g_PC[NB*DD*DD*NO];

// ---------------- helpers ----------------
// fp32 pair -> (hi, lo) bf16x2
__device__ __forceinline__ void split_pair(float a, float b, uint32_t& hi, uint32_t& lo) {
    __nv_bfloat162 h = __floats2bfloat162_rn(a, b);
    float2 hf = __bfloat1622float2(h);
    __nv_bfloat162 l = __floats2bfloat162_rn(a - hf.x, b - hf.y);
    hi = *(uint32_t*)&h;
    lo = *(uint32_t*)&l;
}

#define MMA16816(d, a, b) \
    asm volatile("mma.sync.aligned.m16n8k16.row.col.f32.bf16.bf16.f32 " \
                 "{%0,%1,%2,%3}, {%4,%5,%6,%7}, {%8,%9}, {%0,%1,%2,%3};" \
                 : "+f"(d[0]), "+f"(d[1]), "+f"(d[2]), "+f"(d[3]) \
                 : "r"(a[0]), "r"(a[1]), "r"(a[2]), "r"(a[3]), "r"(b[0]), "r"(b[1]))

// ---------------- K1: axis sums (grid 768) ----------------
__global__ __launch_bounds__(256) void k_means(const float* __restrict__ x) {
    int sel = blockIdx.x >> 8;
    int blk = blockIdx.x & 255;
    int b = blk >> 5, d = blk & 31;
    int t = threadIdx.x;
    const float4* x4 = (const float4*)x;

    if (sel == 0) {
        float4 acc = make_float4(0.f, 0.f, 0.f, 0.f);
        #pragma unroll 8
        for (int i = 0; i < DD; i++) {
            float4 v = x4[((b * DD + i) * DD + d) * 256 + t];
            acc.x += v.x; acc.y += v.y; acc.z += v.z; acc.w += v.w;
        }
        ((float4*)g_m1)[(b * DD + d) * 256 + t] = acc;
    } else if (sel == 1) {
        float4 acc = make_float4(0.f, 0.f, 0.f, 0.f);
        #pragma unroll 8
        for (int j = 0; j < DD; j++) {
            float4 v = x4[((b * DD + d) * DD + j) * 256 + t];
            acc.x += v.x; acc.y += v.y; acc.z += v.z; acc.w += v.w;
        }
        ((float4*)g_m2)[(b * DD + d) * 256 + t] = acc;
    } else {
        int j = t >> 3, c4 = t & 7;
        float4 acc = make_float4(0.f, 0.f, 0.f, 0.f);
        #pragma unroll 8
        for (int k = 0; k < DD; k++) {
            float4 v = x4[((b * DD + d) * DD + j) * 256 + k * 8 + c4];
            acc.x += v.x; acc.y += v.y; acc.z += v.z; acc.w += v.w;
        }
        ((float4*)g_m3)[(b * DD + d) * 256 + j * 8 + c4] = acc;
    }
}

// ---------------- K2: pools + small projections (grid 776) ----------------
__global__ __launch_bounds__(128) void k_small(const float* __restrict__ W,
                                               const float* __restrict__ bias) {
    __shared__ float part[128];
    __shared__ float mrow[NC];
    int gid = blockIdx.x;
    int t = threadIdx.x;
    int c = t & 31, q = t >> 5;

    float s = 0.f;
    const float* w;
    float scale;
    float* dst;
    bool addb = false;

    if (gid < 256) {
        int b = gid >> 5, k = gid & 31;
        #pragma unroll
        for (int j = q; j < DD; j += 4) s += g_m1[((b * DD + j) * DD + k) * NC + c];
        w = W + 128; scale = 1.0f / 1024.0f; dst = g_pij + gid * NO;
    } else if (gid < 512) {
        int g = gid - 256;
        int b = g >> 5, j = g & 31;
        #pragma unroll
        for (int k = q; k < DD; k += 4) s += g_m1[((b * DD + j) * DD + k) * NC + c];
        w = W + 160; scale = 1.0f / 1024.0f; dst = g_pik + g * NO;
    } else if (gid < 768) {
        int g = gid - 512;
        int b = g >> 5, i = g & 31;
        #pragma unroll
        for (int k = q; k < DD; k += 4) s += g_m2[((b * DD + i) * DD + k) * NC + c];
        w = W + 192; scale = 1.0f / 1024.0f; dst = g_pjk + g * NO;
    } else {
        int b = gid - 768;
        for (int jk = q; jk < DD * DD; jk += 4) s += g_m1[(b * DD * DD + jk) * NC + c];
        w = W + 224; scale = 1.0f / 32768.0f; dst = g_pall + b * NO; addb = true;
    }
    part[t] = s;
    __syncthreads();
    if (t < 32) mrow[t] = part[t] + part[t + 32] + part[t + 64] + part[t + 96];
    __syncthreads();
    if (t < 32) {
        float acc = 0.f;
        #pragma unroll
        for (int cc = 0; cc < NC; cc++) acc += mrow[cc] * w[t * 256 + cc];
        acc *= scale;
        if (addb) acc += bias[t];
        dst[t] = acc;
    }
}

// ---------------- shared mma tile machinery ----------------
#define XRS 40

// stage 128 rows of [row][32f] from src into x_s (stride XRS), coalesced
__device__ __forceinline__ void stage_rows(const float* __restrict__ src, float* x_s, int tid) {
    const float4* xg = (const float4*)src;
    #pragma unroll
    for (int q = 0; q < 8; q++) {
        int idx = q * 128 + tid;
        int row = idx >> 3, c4 = idx & 7;
        *(float4*)(x_s + row * XRS + c4 * 4) = xg[idx];
    }
}

// B fragments from W_s (stride XRS), split bf16
__device__ __forceinline__ void make_bfrags(const float* W_s, int lr, int lc2,
                                            uint32_t Bh[2][4][2], uint32_t Bl[2][4][2]) {
    #pragma unroll
    for (int kc = 0; kc < 2; kc++) {
        #pragma unroll
        for (int nc = 0; nc < 4; nc++) {
            int o = nc * 8 + lr;
            int c = kc * 16 + lc2;
            float2 w0 = *(const float2*)(W_s + o * XRS + c);
            float2 w1 = *(const float2*)(W_s + o * XRS + c + 8);
            split_pair(w0.x, w0.y, Bh[kc][nc][0], Bl[kc][nc][0]);
            split_pair(w1.x, w1.y, Bh[kc][nc][1], Bl[kc][nc][1]);
        }
    }
}

// two m16n32 tiles per warp over x_s rows [wid*32, wid*32+32), D back into x_s
__device__ __forceinline__ void mma_tiles(float* x_s, int wid, int lr, int lc2,
                                          uint32_t Bh[2][4][2], uint32_t Bl[2][4][2]) {
    #pragma unroll
    for (int t = 0; t < 2; t++) {
        int rbase = wid * 32 + t * 16;
        uint32_t Ah[2][4], Al[2][4];
        #pragma unroll
        for (int kc = 0; kc < 2; kc++) {
            int c = kc * 16 + lc2;
            const float* r0 = x_s + (rbase + lr) * XRS;
            const float* r1 = x_s + (rbase + lr + 8) * XRS;
            float2 f0 = *(const float2*)(r0 + c);
            float2 f1 = *(const float2*)(r1 + c);
            float2 f2 = *(const float2*)(r0 + c + 8);
            float2 f3 = *(const float2*)(r1 + c + 8);
            split_pair(f0.x, f0.y, Ah[kc][0], Al[kc][0]);
            split_pair(f1.x, f1.y, Ah[kc][1], Al[kc][1]);
            split_pair(f2.x, f2.y, Ah[kc][2], Al[kc][2]);
            split_pair(f3.x, f3.y, Ah[kc][3], Al[kc][3]);
        }

        float D[4][4];
        #pragma unroll
        for (int nc = 0; nc < 4; nc++)
            #pragma unroll
            for (int q = 0; q < 4; q++) D[nc][q] = 0.f;

        #pragma unroll
        for (int kc = 0; kc < 2; kc++) {
            #pragma unroll
            for (int nc = 0; nc < 4; nc++) {
                MMA16816(D[nc], Ah[kc], Bh[kc][nc]);
                MMA16816(D[nc], Ah[kc], Bl[kc][nc]);
                MMA16816(D[nc], Al[kc], Bh[kc][nc]);
            }
        }

        #pragma unroll
        for (int half = 0; half < 2; half++) {
            int row = rbase + lr + half * 8;
            #pragma unroll
            for (int nc = 0; nc < 4; nc++) {
                *(float2*)(x_s + row * XRS + nc * 8 + lc2) =
                    make_float2(D[nc][half * 2 + 0], D[nc][half * 2 + 1]);
            }
        }
    }
}

// ---------------- K3: PA/PB/PC projections via mma.sync (grid 192 x 128) ----------------
__global__ __launch_bounds__(128) void k_bigproj_mma(const float* __restrict__ W) {
    __shared__ __align__(16) float x_s[128 * XRS];
    __shared__ __align__(16) float W_s[32 * XRS];

    int tid = threadIdx.x;
    int wid = tid >> 5, lid = tid & 31;
    int lr = lid >> 2, lc2 = (lid & 3) * 2;
    int sel = blockIdx.x >> 6;       // 0:PA(m1) 1:PB(m2) 2:PC(m3)
    int r0 = (blockIdx.x & 63) * 128;
    const float* src = (sel == 0) ? g_m1 : (sel == 1) ? g_m2 : g_m3;
    float* dstbase = (sel == 0) ? g_PA : (sel == 1) ? g_PB : g_PC;

    // stage W group (1+sel), pre-scaled by 1/32
    #pragma unroll
    for (int idx = tid; idx < 256; idx += 128) {
        int o = idx >> 3, c4 = idx & 7;
        float4 v = *(const float4*)(W + o * 256 + (1 + sel) * 32 + c4 * 4);
        v.x *= (1.0f / 32.0f); v.y *= (1.0f / 32.0f);
        v.z *= (1.0f / 32.0f); v.w *= (1.0f / 32.0f);
        *(float4*)(W_s + o * XRS + c4 * 4) = v;
    }
    stage_rows(src + (size_t)r0 * 32, x_s, tid);
    __syncthreads();

    uint32_t Bh[2][4][2], Bl[2][4][2];
    make_bfrags(W_s, lr, lc2, Bh, Bl);
    mma_tiles(x_s, wid, lr, lc2, Bh, Bl);
    __syncthreads();

    // coalesced epilogue with pool adds
    #pragma unroll
    for (int q = 0; q < 8; q++) {
        int idx = q * 128 + tid;
        int rl = idx >> 3, o4 = idx & 7;
        int p = r0 + rl;
        int b = p >> 10, d1 = (p >> 5) & 31, d2 = p & 31;
        float4 v = *(const float4*)(x_s + rl * XRS + o4 * 4);
        if (sel == 0) {
            float4 a = ((const float4*)(g_pij + (b * 32 + d2) * 32))[o4];   // [b][k]
            float4 bq = ((const float4*)(g_pik + (b * 32 + d1) * 32))[o4];  // [b][j]
            float4 c = ((const float4*)(g_pall + b * 32))[o4];
            v.x += a.x + bq.x + c.x; v.y += a.y + bq.y + c.y;
            v.z += a.z + bq.z + c.z; v.w += a.w + bq.w + c.w;
        } else if (sel == 1) {
            float4 a = ((const float4*)(g_pjk + (b * 32 + d1) * 32))[o4];   // [b][i]
            v.x += a.x; v.y += a.y; v.z += a.z; v.w += a.w;
        }
        ((float4*)(dstbase + (size_t)p * 32))[o4] = v;
    }
}

// ---------------- K4: main projection via mma.sync (grid 2048 x 128) ----------------
__global__ __launch_bounds__(128) void k_main_mma(const float* __restrict__ x,
                                                  const float* __restrict__ W,
                                                  float* __restrict__ out) {
    __shared__ __align__(16) float x_s[128 * XRS];
    __shared__ __align__(16) float W_s[32 * XRS];

    int tid = threadIdx.x;
    int wid = tid >> 5, lid = tid & 31;
    int lr = lid >> 2, lc2 = (lid & 3) * 2;
    int p0 = blockIdx.x * 128;

    #pragma unroll
    for (int idx = tid; idx < 256; idx += 128) {
        int o = idx >> 3, c4 = idx & 7;
        *(float4*)(W_s + o * XRS + c4 * 4) = *(const float4*)(W + o * 256 + c4 * 4);
    }
    stage_rows(x + (size_t)p0 * 32, x_s, tid);
    __syncthreads();

    uint32_t Bh[2][4][2], Bl[2][4][2];
    make_bfrags(W_s, lr, lc2, Bh, Bl);
    mma_tiles(x_s, wid, lr, lc2, Bh, Bl);
    __syncthreads();

    // coalesced epilogue: + PA + PB + PC
    float4* og4 = (float4*)(out + (size_t)p0 * 32);
    #pragma unroll
    for (int q = 0; q < 8; q++) {
        int idx = q * 128 + tid;
        int rl = idx >> 3, o4 = idx & 7;
        int gr = p0 + rl;
        int k = gr & 31, j = (gr >> 5) & 31, i = (gr >> 10) & 31, b = gr >> 15;
        float4 v = *(const float4*)(x_s + rl * XRS + o4 * 4);
        float4 pa = ((const float4*)(g_PA + (((b * 32 + j) * 32 + k) * 32)))[o4];
        float4 pb = ((const float4*)(g_PB + (((b * 32 + i) * 32 + k) * 32)))[o4];
        float4 pc = ((const float4*)(g_PC + (((b * 32 + i) * 32 + j) * 32)))[o4];
        float4 r;
        r.x = v.x + pa.x + pb.x + pc.x;
        r.y = v.y + pa.y + pb.y + pc.y;
        r.z = v.z + pa.z + pb.z + pc.z;
        r.w = v.w + pa.w + pb.w + pc.w;
        og4[idx] = r;
    }
}

// ---------------- launch ----------------
extern "C" void kernel_launch(void* const* d_in, const int* in_sizes, int n_in,
                              void* d_out, int out_size) {
    const float* x    = (const float*)d_in[0];
    const float* W    = (const float*)d_in[1];
    const float* bias = (const float*)d_in[2];
    float* out = (float*)d_out;

    k_means<<<768, 256>>>(x);
    k_small<<<776, 128>>>(W, bias);
    k_bigproj_mma<<<192, 128>>>(W);
    k_main_mma<<<2048, 128>>>(x, W, out);
}